// round 2
// baseline (speedup 1.0000x reference)
#include <cuda_runtime.h>

#define NN    128
#define BATCH 2
#define LL    2048
#define CH    32          // chunk length S
#define NG    (LL/CH)     // 64 chunks per batch

// ---- device scratch (no allocation allowed) ----
__device__ float g_Ad[NN*NN];
__device__ float g_Bd[NN];
__device__ float g_pow[2][NN*NN];      // for Ad^S via squaring
__device__ float g_h[BATCH*NG*NN];     // local chunk contributions
__device__ float g_bound[BATCH*NG*NN]; // state entering each chunk
__device__ float g_states[BATCH*LL*NN];

// ============================================================
// Kernel 1: discretize. P1 = I - 0.5A (lower triangular).
// Gauss elimination of [P1 | I] -> Minv, Ad = 2*Minv - I, Bd = Minv*B.
// ============================================================
__global__ __launch_bounds__(1024) void k_disc(const float* __restrict__ A,
                                               const float* __restrict__ B) {
    extern __shared__ float sm[];
    float* sP = sm;          // NN*NN
    float* sM = sm + NN*NN;  // NN*NN
    int tid = threadIdx.x;
    for (int idx = tid; idx < NN*NN; idx += 1024) {
        int i = idx >> 7, j = idx & (NN-1);
        float iv = (i == j) ? 1.0f : 0.0f;
        sP[idx] = iv - 0.5f * A[idx];
        sM[idx] = iv;
    }
    __syncthreads();
    for (int k = 0; k < NN; k++) {
        float inv = 1.0f / sP[k*NN + k];
        if (tid < NN) sM[k*NN + tid] *= inv;
        __syncthreads();
        int rows = NN - 1 - k;
        for (int idx = tid; idx < rows*NN; idx += 1024) {
            int i = k + 1 + (idx >> 7);
            int j = idx & (NN-1);
            sM[i*NN + j] -= sP[i*NN + k] * sM[k*NN + j];
        }
        __syncthreads();
    }
    for (int idx = tid; idx < NN*NN; idx += 1024) {
        int i = idx >> 7, j = idx & (NN-1);
        float ad = 2.0f * sM[idx] - ((i == j) ? 1.0f : 0.0f);
        g_Ad[idx] = ad;
        g_pow[0][idx] = ad;
    }
    if (tid < NN) {
        float acc = 0.0f;
        for (int j = 0; j < NN; j++) acc += sM[tid*NN + j] * B[j];
        g_Bd[tid] = acc;
    }
}

// ============================================================
// Kernel 2: matrix squaring  g_pow[dst] = g_pow[src]^2   (128x128x128)
// 16 blocks x 256 threads; block owns 8 rows; thread -> 4 cols (float4).
// ============================================================
__global__ __launch_bounds__(256) void k_sq(int srcSel, int dstSel) {
    extern __shared__ float sm[];
    float* sB = sm;           // NN*NN
    float* sA = sm + NN*NN;   // 8*NN
    const float* src = g_pow[srcSel];
    float*       dst = g_pow[dstSel];
    int tid = threadIdx.x;
    int r0  = blockIdx.x * 8;
    for (int idx = tid; idx < NN*NN/4; idx += 256)
        ((float4*)sB)[idx] = ((const float4*)src)[idx];
    for (int idx = tid; idx < 8*NN/4; idx += 256)
        ((float4*)sA)[idx] = ((const float4*)src)[r0*(NN/4) + idx];
    __syncthreads();
    int r  = tid >> 5;        // 0..7
    int c4 = tid & 31;        // float4 column
    const float4* sB4 = (const float4*)sB;
    float4 acc = make_float4(0.f, 0.f, 0.f, 0.f);
    #pragma unroll 4
    for (int k = 0; k < NN; k++) {
        float  a  = sA[r*NN + k];
        float4 bv = sB4[k*(NN/4) + c4];
        acc.x = fmaf(a, bv.x, acc.x);
        acc.y = fmaf(a, bv.y, acc.y);
        acc.z = fmaf(a, bv.z, acc.z);
        acc.w = fmaf(a, bv.w, acc.w);
    }
    ((float4*)dst)[(r0 + r)*(NN/4) + c4] = acc;
}

// ============================================================
// Kernel 3/5: chunk recurrence. MODE 0: zero init, emit chunk-final h.
//             MODE 1: init from g_bound, emit all states (+ c_fin).
// 128 threads; each thread owns one row of Ad in registers.
// ============================================================
template <int MODE>
__global__ __launch_bounds__(NN) void k_phase(const float* __restrict__ f,
                                              float* __restrict__ cfin) {
    extern __shared__ float sm[];
    float* sAd = sm;               // NN*129 padded
    float* sc  = sm + NN*129;      // NN
    float* sf  = sc + NN;          // CH
    int tid = threadIdx.x;
    int g = blockIdx.x, b = blockIdx.y;

    for (int idx = tid; idx < NN*NN; idx += NN) {
        int i = idx >> 7, j = idx & (NN-1);
        sAd[i*129 + j] = g_Ad[idx];
    }
    if (tid < CH) sf[tid] = f[b*LL + g*CH + tid];
    sc[tid] = (MODE == 0) ? 0.0f : g_bound[(b*NG + g)*NN + tid];
    __syncthreads();

    float a[NN];
    #pragma unroll
    for (int j = 0; j < NN; j++) a[j] = sAd[tid*129 + j];
    float bd = g_Bd[tid];
    float* st = g_states + (size_t)(b*LL + g*CH)*NN;

    for (int t = 0; t < CH; t++) {
        float ft = sf[t];
        float acc0 = bd * ft, acc1 = 0.f, acc2 = 0.f, acc3 = 0.f;
        const float4* sc4 = (const float4*)sc;
        #pragma unroll
        for (int j4 = 0; j4 < NN/4; j4++) {
            float4 v = sc4[j4];
            acc0 = fmaf(a[4*j4+0], v.x, acc0);
            acc1 = fmaf(a[4*j4+1], v.y, acc1);
            acc2 = fmaf(a[4*j4+2], v.z, acc2);
            acc3 = fmaf(a[4*j4+3], v.w, acc3);
        }
        float cn = (acc0 + acc1) + (acc2 + acc3);
        __syncthreads();
        sc[tid] = cn;
        if (MODE == 1) st[t*NN + tid] = cn;
        __syncthreads();
    }
    if (MODE == 0) {
        g_h[(b*NG + g)*NN + tid] = sc[tid];
    } else if (g == NG-1 && cfin != nullptr) {
        cfin[b*NN + tid] = sc[tid];
    }
}

// ============================================================
// Kernel 4: boundary prefix. bound[g] = state entering chunk g.
//           C_{g+1} = Ad^S * C_g + h_g.  One block per batch.
// ============================================================
__global__ __launch_bounds__(NN) void k_phaseB() {
    extern __shared__ float sm[];
    float* sA = sm;             // NN*129
    float* sc = sm + NN*129;    // NN
    int tid = threadIdx.x;
    int b = blockIdx.x;
    const float* AdS = g_pow[1];   // Ad^32 after 5 squarings
    for (int idx = tid; idx < NN*NN; idx += NN) {
        int i = idx >> 7, j = idx & (NN-1);
        sA[i*129 + j] = AdS[idx];
    }
    sc[tid] = 0.0f;
    __syncthreads();
    float a[NN];
    #pragma unroll
    for (int j = 0; j < NN; j++) a[j] = sA[tid*129 + j];

    for (int g = 0; g < NG; g++) {
        g_bound[(b*NG + g)*NN + tid] = sc[tid];
        float acc0 = g_h[(b*NG + g)*NN + tid], acc1 = 0.f, acc2 = 0.f, acc3 = 0.f;
        const float4* sc4 = (const float4*)sc;
        #pragma unroll
        for (int j4 = 0; j4 < NN/4; j4++) {
            float4 v = sc4[j4];
            acc0 = fmaf(a[4*j4+0], v.x, acc0);
            acc1 = fmaf(a[4*j4+1], v.y, acc1);
            acc2 = fmaf(a[4*j4+2], v.z, acc2);
            acc3 = fmaf(a[4*j4+3], v.w, acc3);
        }
        float cn = (acc0 + acc1) + (acc2 + acc3);
        __syncthreads();
        sc[tid] = cn;
        __syncthreads();
    }
}

// ============================================================
// Kernel 6: expand. ys[b,t,n,k] = C[n]*c_t[b,k] + D*f[b,t].
// One block per (b,t): writes 64KB coalesced (STG.128). DRAM-bound.
// ============================================================
__global__ __launch_bounds__(256) void k_expand(const float* __restrict__ f,
                                                const float* __restrict__ Cv,
                                                const float* __restrict__ Dv,
                                                float* __restrict__ ys) {
    __shared__ float  sC[NN];
    __shared__ float4 scv[NN/4];
    int tid = threadIdx.x;
    int t = blockIdx.x, b = blockIdx.y;
    if (tid < NN)   sC[tid]  = Cv[tid];
    if (tid < NN/4) scv[tid] = ((const float4*)(g_states + (size_t)(b*LL + t)*NN))[tid];
    __syncthreads();
    int lane = tid & 31, w = tid >> 5;
    float4 cv = scv[lane];
    float  df = Dv[0] * f[b*LL + t];
    float4* out = (float4*)(ys + (size_t)(b*LL + t) * NN * NN);
    #pragma unroll
    for (int n = w; n < NN; n += 8) {
        float cn = sC[n];
        float4 v;
        v.x = fmaf(cn, cv.x, df);
        v.y = fmaf(cn, cv.y, df);
        v.z = fmaf(cn, cv.z, df);
        v.w = fmaf(cn, cv.w, df);
        out[n*(NN/4) + lane] = v;
    }
}

// ============================================================
extern "C" void kernel_launch(void* const* d_in, const int* in_sizes, int n_in,
                              void* d_out, int out_size) {
    const float* f = (const float*)d_in[0];
    const float* A = (const float*)d_in[1];
    const float* B = (const float*)d_in[2];
    const float* C = (const float*)d_in[3];
    const float* D = (const float*)d_in[4];
    float* out = (float*)d_out;

    const long long ysz = (long long)BATCH * LL * NN * NN;   // 67108864
    const int cf = BATCH * NN;                               // 256
    float* cfin = nullptr;
    float* ys   = out;
    if ((long long)out_size == ysz + cf) { cfin = out; ys = out + cf; }

    const int smem_disc  = 2*NN*NN*4;                 // 131072
    const int smem_sq    = (NN*NN + 8*NN)*4;          // 69632
    const int smem_phase = (NN*129 + NN + CH)*4;      // 66688
    const int smem_pB    = (NN*129 + NN)*4;           // 66560
    cudaFuncSetAttribute(k_disc,     cudaFuncAttributeMaxDynamicSharedMemorySize, smem_disc);
    cudaFuncSetAttribute(k_sq,       cudaFuncAttributeMaxDynamicSharedMemorySize, smem_sq);
    cudaFuncSetAttribute(k_phase<0>, cudaFuncAttributeMaxDynamicSharedMemorySize, smem_phase);
    cudaFuncSetAttribute(k_phase<1>, cudaFuncAttributeMaxDynamicSharedMemorySize, smem_phase);
    cudaFuncSetAttribute(k_phaseB,   cudaFuncAttributeMaxDynamicSharedMemorySize, smem_pB);

    // 1) discretize
    k_disc<<<1, 1024, smem_disc>>>(A, B);
    // 2) Ad^32 via 5 squarings: pow0=Ad -> pow1=Ad^2 -> pow0=Ad^4 -> pow1=Ad^8
    //    -> pow0=Ad^16 -> pow1=Ad^32
    k_sq<<<16, 256, smem_sq>>>(0, 1);
    k_sq<<<16, 256, smem_sq>>>(1, 0);
    k_sq<<<16, 256, smem_sq>>>(0, 1);
    k_sq<<<16, 256, smem_sq>>>(1, 0);
    k_sq<<<16, 256, smem_sq>>>(0, 1);
    // 3) phase A: local chunk contributions (parallel over 128 chunks)
    dim3 gA(NG, BATCH);
    k_phase<0><<<gA, NN, smem_phase>>>(f, nullptr);
    // 4) phase B: boundary prefix (sequential over 64 chunks, per-batch block)
    k_phaseB<<<BATCH, NN, smem_pB>>>();
    // 5) phase C: recompute all states from correct boundaries (+ c_fin)
    k_phase<1><<<gA, NN, smem_phase>>>(f, cfin);
    // 6) expand: 268 MB broadcast write (DRAM-bound)
    dim3 gE(LL, BATCH);
    k_expand<<<gE, 256>>>(f, C, D, ys);
}

// round 4
// speedup vs baseline: 1.1592x; 1.1592x over previous
#include <cuda_runtime.h>

#define NN    128
#define BATCH 2
#define LL    2048
#define CH    32          // chunk length S
#define NG    (LL/CH)     // 64 chunks per batch

// ---- device scratch (no allocation allowed) ----
__device__ float g_Ad[NN*NN];
__device__ float g_Bd[NN];
__device__ float g_pow[2][NN*NN];      // for Ad^S via squaring
__device__ float g_h[BATCH*NG*NN];     // local chunk contributions
__device__ float g_bound[BATCH*NG*NN]; // state entering each chunk

// ============================================================
// Kernel 1: discretize. P1 = I - 0.5A (LOWER TRIANGULAR).
// Since P1 is triangular, no pivot updates are ever needed:
// right-looking elimination with ORIGINAL multipliers, rows kept
// unscaled (diag folded into multiplier) -> ONE barrier per pivot.
// Ad = 2*Minv - I, Bd = Minv*B.
// ============================================================
__global__ __launch_bounds__(1024) void k_disc(const float* __restrict__ A,
                                               const float* __restrict__ B) {
    extern __shared__ float sm[];
    float* sL = sm;          // NN*NN  original P1
    float* sU = sm + NN*NN;  // NN*NN  unscaled Minv rows
    __shared__ float sinv[NN];
    int tid = threadIdx.x;
    for (int idx = tid; idx < NN*NN; idx += 1024) {
        int i = idx >> 7, j = idx & (NN-1);
        float iv = (i == j) ? 1.0f : 0.0f;
        sL[idx] = iv - 0.5f * A[idx];
        sU[idx] = iv;
    }
    if (tid < NN) sinv[tid] = 1.0f / (1.0f - 0.5f * A[tid*NN + tid]);
    __syncthreads();
    for (int k = 0; k < NN-1; k++) {
        float ik = sinv[k];
        int rows = NN - 1 - k;
        const float* uk = sU + k*NN;
        for (int idx = tid; idx < rows*NN; idx += 1024) {
            int i = k + 1 + (idx >> 7);
            int j = idx & (NN-1);
            sU[i*NN + j] -= sL[i*NN + k] * ik * uk[j];
        }
        __syncthreads();
    }
    for (int idx = tid; idx < NN*NN; idx += 1024) {
        int i = idx >> 7, j = idx & (NN-1);
        float x = sinv[i] * sU[idx];
        float ad = 2.0f * x - ((i == j) ? 1.0f : 0.0f);
        g_Ad[idx] = ad;
        g_pow[0][idx] = ad;
    }
    if (tid < NN) {
        float acc = 0.0f;
        float ii = sinv[tid];
        for (int j = 0; j < NN; j++) acc += ii * sU[tid*NN + j] * B[j];
        g_Bd[tid] = acc;
    }
}

// ============================================================
// Kernel 2: matrix squaring, row-per-block.
// 128 blocks x 128 threads; src is 64KB -> L2 resident. High MLP LDG.
// ============================================================
__global__ __launch_bounds__(NN) void k_sq(int srcSel, int dstSel) {
    __shared__ float sa[NN];
    const float* __restrict__ src = g_pow[srcSel];
    float*       __restrict__ dst = g_pow[dstSel];
    int i = blockIdx.x;
    int j = threadIdx.x;
    sa[j] = src[i*NN + j];
    __syncthreads();
    float acc0 = 0.f, acc1 = 0.f, acc2 = 0.f, acc3 = 0.f;
    #pragma unroll
    for (int k = 0; k < NN; k += 4) {
        acc0 = fmaf(sa[k+0], __ldg(src + (k+0)*NN + j), acc0);
        acc1 = fmaf(sa[k+1], __ldg(src + (k+1)*NN + j), acc1);
        acc2 = fmaf(sa[k+2], __ldg(src + (k+2)*NN + j), acc2);
        acc3 = fmaf(sa[k+3], __ldg(src + (k+3)*NN + j), acc3);
    }
    dst[i*NN + j] = (acc0 + acc1) + (acc2 + acc3);
}

// ============================================================
// Kernel 3: phase A. Local chunk contributions from zero state.
// 128 threads; each thread owns one row of Ad in registers.
// ============================================================
__global__ __launch_bounds__(NN) void k_phaseA(const float* __restrict__ f) {
    extern __shared__ float sm[];
    float* sAd = sm;               // NN*129 padded
    float* sc  = sm + NN*129;      // NN
    float* sf  = sc + NN;          // CH
    int tid = threadIdx.x;
    int g = blockIdx.x, b = blockIdx.y;

    for (int idx = tid; idx < NN*NN; idx += NN) {
        int i = idx >> 7, j = idx & (NN-1);
        sAd[i*129 + j] = g_Ad[idx];
    }
    if (tid < CH) sf[tid] = f[b*LL + g*CH + tid];
    sc[tid] = 0.0f;
    __syncthreads();

    float a[NN];
    #pragma unroll
    for (int j = 0; j < NN; j++) a[j] = sAd[tid*129 + j];
    float bd = g_Bd[tid];

    float cn = 0.0f;
    for (int t = 0; t < CH; t++) {
        float ft = sf[t];
        float acc0 = bd * ft, acc1 = 0.f, acc2 = 0.f, acc3 = 0.f;
        const float4* sc4 = (const float4*)sc;
        #pragma unroll
        for (int j4 = 0; j4 < NN/4; j4++) {
            float4 v = sc4[j4];
            acc0 = fmaf(a[4*j4+0], v.x, acc0);
            acc1 = fmaf(a[4*j4+1], v.y, acc1);
            acc2 = fmaf(a[4*j4+2], v.z, acc2);
            acc3 = fmaf(a[4*j4+3], v.w, acc3);
        }
        cn = (acc0 + acc1) + (acc2 + acc3);
        __syncthreads();
        sc[tid] = cn;
        __syncthreads();
    }
    g_h[(b*NG + g)*NN + tid] = cn;
}

// ============================================================
// Kernel 4: boundary prefix. bound[g] = state entering chunk g.
//           C_{g+1} = Ad^S * C_g + h_g.  One block per batch.
// ============================================================
__global__ __launch_bounds__(NN) void k_phaseB() {
    extern __shared__ float sm[];
    float* sA = sm;             // NN*129
    float* sc = sm + NN*129;    // NN
    int tid = threadIdx.x;
    int b = blockIdx.x;
    const float* AdS = g_pow[1];   // Ad^32 after 5 squarings
    for (int idx = tid; idx < NN*NN; idx += NN) {
        int i = idx >> 7, j = idx & (NN-1);
        sA[i*129 + j] = AdS[idx];
    }
    sc[tid] = 0.0f;
    __syncthreads();
    float a[NN];
    #pragma unroll
    for (int j = 0; j < NN; j++) a[j] = sA[tid*129 + j];

    for (int g = 0; g < NG; g++) {
        g_bound[(b*NG + g)*NN + tid] = sc[tid];
        float acc0 = g_h[(b*NG + g)*NN + tid], acc1 = 0.f, acc2 = 0.f, acc3 = 0.f;
        const float4* sc4 = (const float4*)sc;
        #pragma unroll
        for (int j4 = 0; j4 < NN/4; j4++) {
            float4 v = sc4[j4];
            acc0 = fmaf(a[4*j4+0], v.x, acc0);
            acc1 = fmaf(a[4*j4+1], v.y, acc1);
            acc2 = fmaf(a[4*j4+2], v.z, acc2);
            acc3 = fmaf(a[4*j4+3], v.w, acc3);
        }
        float cn = (acc0 + acc1) + (acc2 + acc3);
        __syncthreads();
        sc[tid] = cn;
        __syncthreads();
    }
}

// ============================================================
// Kernel 5: FUSED phase C + expand. Recompute states from correct
// boundary and immediately stream ys[b,t,n,k] = C[n]*c_t[k] + D*f_t.
// The per-step 64KB store stream overlaps the matvec; DRAM-bound.
// ============================================================
__global__ __launch_bounds__(NN) void k_fusedC(const float* __restrict__ f,
                                               const float* __restrict__ Cv,
                                               const float* __restrict__ Dv,
                                               float* __restrict__ ys,
                                               float* __restrict__ cfin) {
    extern __shared__ float sm[];
    float* sAd = sm;               // NN*129 padded
    float* sc  = sm + NN*129;      // NN
    float* sf  = sc + NN;          // CH
    float* sC  = sf + CH;          // NN
    int tid = threadIdx.x;
    int g = blockIdx.x, b = blockIdx.y;

    for (int idx = tid; idx < NN*NN; idx += NN) {
        int i = idx >> 7, j = idx & (NN-1);
        sAd[i*129 + j] = g_Ad[idx];
    }
    if (tid < CH) sf[tid] = f[b*LL + g*CH + tid];
    sC[tid] = Cv[tid];
    sc[tid] = g_bound[(b*NG + g)*NN + tid];
    __syncthreads();

    float a[NN];
    #pragma unroll
    for (int j = 0; j < NN; j++) a[j] = sAd[tid*129 + j];
    float bd  = g_Bd[tid];
    float dv0 = Dv[0];
    int lane = tid & 31, w = tid >> 5;
    float4* outbase = (float4*)(ys + (size_t)(b*LL + g*CH) * NN * NN);

    float cn = 0.0f;
    for (int t = 0; t < CH; t++) {
        float ft = sf[t];
        float acc0 = bd * ft, acc1 = 0.f, acc2 = 0.f, acc3 = 0.f;
        const float4* sc4 = (const float4*)sc;
        #pragma unroll
        for (int j4 = 0; j4 < NN/4; j4++) {
            float4 v = sc4[j4];
            acc0 = fmaf(a[4*j4+0], v.x, acc0);
            acc1 = fmaf(a[4*j4+1], v.y, acc1);
            acc2 = fmaf(a[4*j4+2], v.z, acc2);
            acc3 = fmaf(a[4*j4+3], v.w, acc3);
        }
        cn = (acc0 + acc1) + (acc2 + acc3);
        __syncthreads();
        sc[tid] = cn;
        __syncthreads();
        // stream the 64KB output tile for time t (coalesced STG.128)
        float4 cv = ((const float4*)sc)[lane];
        float  df = dv0 * ft;
        float4* out = outbase + (size_t)t * (NN*NN/4);
        #pragma unroll
        for (int n = w; n < NN; n += 4) {
            float c_ = sC[n];
            float4 v;
            v.x = fmaf(c_, cv.x, df);
            v.y = fmaf(c_, cv.y, df);
            v.z = fmaf(c_, cv.z, df);
            v.w = fmaf(c_, cv.w, df);
            out[n*(NN/4) + lane] = v;
        }
    }
    if (cfin != nullptr && g == NG-1)
        cfin[b*NN + tid] = cn;
}

// ============================================================
extern "C" void kernel_launch(void* const* d_in, const int* in_sizes, int n_in,
                              void* d_out, int out_size) {
    const float* f = (const float*)d_in[0];
    const float* A = (const float*)d_in[1];
    const float* B = (const float*)d_in[2];
    const float* C = (const float*)d_in[3];
    const float* D = (const float*)d_in[4];
    float* out = (float*)d_out;

    const long long ysz = (long long)BATCH * LL * NN * NN;   // 67108864
    const int cf = BATCH * NN;                               // 256
    float* cfin = nullptr;
    float* ys   = out;
    if ((long long)out_size == ysz + cf) { cfin = out; ys = out + cf; }

    const int smem_disc  = 2*NN*NN*4;                 // 131072
    const int smem_pA    = (NN*129 + NN + CH)*4;      // 66688
    const int smem_pB    = (NN*129 + NN)*4;           // 66560
    const int smem_fC    = (NN*129 + NN + CH + NN)*4; // 67200
    cudaFuncSetAttribute(k_disc,   cudaFuncAttributeMaxDynamicSharedMemorySize, smem_disc);
    cudaFuncSetAttribute(k_phaseA, cudaFuncAttributeMaxDynamicSharedMemorySize, smem_pA);
    cudaFuncSetAttribute(k_phaseB, cudaFuncAttributeMaxDynamicSharedMemorySize, smem_pB);
    cudaFuncSetAttribute(k_fusedC, cudaFuncAttributeMaxDynamicSharedMemorySize, smem_fC);

    // 1) discretize
    k_disc<<<1, 1024, smem_disc>>>(A, B);
    // 2) phase A (depends only on Ad/Bd) — local chunk contributions
    dim3 gA(NG, BATCH);
    k_phaseA<<<gA, NN, smem_pA>>>(f);
    // 3) Ad^32 via 5 squarings: pow0=Ad -> pow1 -> pow0 -> pow1 -> pow0 -> pow1
    k_sq<<<NN, NN>>>(0, 1);
    k_sq<<<NN, NN>>>(1, 0);
    k_sq<<<NN, NN>>>(0, 1);
    k_sq<<<NN, NN>>>(1, 0);
    k_sq<<<NN, NN>>>(0, 1);
    // 4) boundary prefix (sequential over 64 chunks, per-batch block)
    k_phaseB<<<BATCH, NN, smem_pB>>>();
    // 5) fused phase C + expand: recompute states, stream 268MB of ys
    k_fusedC<<<gA, NN, smem_fC>>>(f, C, D, ys, cfin);
}

// round 6
// speedup vs baseline: 1.1698x; 1.0091x over previous
#include <cuda_runtime.h>

#define NN    128
#define BATCH 2
#define LL    2048
#define CH    32          // chunk length S
#define NG    (LL/CH)     // 64 chunks per batch
#define NT    512         // threads for split-K kernels (4 quarters x 128 rows)

// ---- device scratch (no allocation allowed) ----
__device__ float g_Ad[NN*NN];
__device__ float g_Bd[NN];
__device__ float g_pow[2][NN*NN];      // for Ad^S via squaring
__device__ float g_h[BATCH*NG*NN];     // local chunk contributions
__device__ float g_bound[BATCH*NG*NN]; // state entering each chunk

// ============================================================
// Kernel 1: discretize. P1 = I - 0.5A (LOWER TRIANGULAR).
// Right-looking elimination, one barrier per pivot.
// Ad = 2*Minv - I, Bd = Minv*B.
// ============================================================
__global__ __launch_bounds__(1024) void k_disc(const float* __restrict__ A,
                                               const float* __restrict__ B) {
    extern __shared__ float sm[];
    float* sL = sm;          // NN*NN  original P1
    float* sU = sm + NN*NN;  // NN*NN  unscaled Minv rows
    __shared__ float sinv[NN];
    int tid = threadIdx.x;
    for (int idx = tid; idx < NN*NN; idx += 1024) {
        int i = idx >> 7, j = idx & (NN-1);
        float iv = (i == j) ? 1.0f : 0.0f;
        sL[idx] = iv - 0.5f * A[idx];
        sU[idx] = iv;
    }
    if (tid < NN) sinv[tid] = 1.0f / (1.0f - 0.5f * A[tid*NN + tid]);
    __syncthreads();
    for (int k = 0; k < NN-1; k++) {
        float ik = sinv[k];
        int rows = NN - 1 - k;
        const float* uk = sU + k*NN;
        for (int idx = tid; idx < rows*NN; idx += 1024) {
            int i = k + 1 + (idx >> 7);
            int j = idx & (NN-1);
            sU[i*NN + j] -= sL[i*NN + k] * ik * uk[j];
        }
        __syncthreads();
    }
    for (int idx = tid; idx < NN*NN; idx += 1024) {
        int i = idx >> 7, j = idx & (NN-1);
        float x = sinv[i] * sU[idx];
        float ad = 2.0f * x - ((i == j) ? 1.0f : 0.0f);
        g_Ad[idx] = ad;
        g_pow[0][idx] = ad;
    }
    if (tid < NN) {
        float acc = 0.0f;
        float ii = sinv[tid];
        for (int j = 0; j < NN; j++) acc += ii * sU[tid*NN + j] * B[j];
        g_Bd[tid] = acc;
    }
}

// ============================================================
// Kernel 2: matrix squaring, row-per-block, MLP=32 batched loads.
// ============================================================
__global__ __launch_bounds__(NN) void k_sq(int srcSel, int dstSel) {
    __shared__ float sa[NN];
    const float* __restrict__ src = g_pow[srcSel];
    float*       __restrict__ dst = g_pow[dstSel];
    int i = blockIdx.x;
    int j = threadIdx.x;
    sa[j] = src[i*NN + j];
    __syncthreads();
    float acc0 = 0.f, acc1 = 0.f, acc2 = 0.f, acc3 = 0.f;
    float bv[32];
    #pragma unroll
    for (int kk = 0; kk < NN; kk += 32) {
        #pragma unroll
        for (int u = 0; u < 32; u++)
            bv[u] = __ldg(src + (kk+u)*NN + j);     // 32 loads in flight
        #pragma unroll
        for (int u = 0; u < 32; u += 4) {
            acc0 = fmaf(sa[kk+u+0], bv[u+0], acc0);
            acc1 = fmaf(sa[kk+u+1], bv[u+1], acc1);
            acc2 = fmaf(sa[kk+u+2], bv[u+2], acc2);
            acc3 = fmaf(sa[kk+u+3], bv[u+3], acc3);
        }
    }
    dst[i*NN + j] = (acc0 + acc1) + (acc2 + acc3);
}

// ============================================================
// Kernel 3: phase A, 512 threads, 4-way split-K.
// Thread (r = tid&127, q = tid>>7) owns Ad[r, 32q:32q+32] in regs.
// ============================================================
__global__ __launch_bounds__(NT) void k_phaseA(const float* __restrict__ f) {
    extern __shared__ float sm[];
    float* sAd = sm;               // NN*129 padded
    float* sc  = sAd + NN*129;     // NN
    float* sf  = sc + NN;          // CH
    float* sp  = sf + CH;          // NT partials
    int tid = threadIdx.x;
    int r = tid & (NN-1), q = tid >> 7;
    int g = blockIdx.x, b = blockIdx.y;

    for (int idx = tid; idx < NN*NN; idx += NT) {
        int i = idx >> 7, j = idx & (NN-1);
        sAd[i*129 + j] = g_Ad[idx];
    }
    if (tid < CH) sf[tid] = f[b*LL + g*CH + tid];
    if (tid < NN) sc[tid] = 0.0f;
    __syncthreads();

    float a[32];
    #pragma unroll
    for (int u = 0; u < 32; u++) a[u] = sAd[r*129 + 32*q + u];
    float bd = (q == 0) ? g_Bd[r] : 0.0f;

    float cn = 0.0f;
    for (int t = 0; t < CH; t++) {
        float acc0 = (q == 0) ? bd * sf[t] : 0.f;
        float acc1 = 0.f, acc2 = 0.f, acc3 = 0.f;
        const float4* sc4 = (const float4*)sc;
        #pragma unroll
        for (int u4 = 0; u4 < 8; u4++) {
            float4 v = sc4[8*q + u4];              // warp-broadcast
            acc0 = fmaf(a[4*u4+0], v.x, acc0);
            acc1 = fmaf(a[4*u4+1], v.y, acc1);
            acc2 = fmaf(a[4*u4+2], v.z, acc2);
            acc3 = fmaf(a[4*u4+3], v.w, acc3);
        }
        sp[q*NN + r] = (acc0 + acc1) + (acc2 + acc3);
        __syncthreads();
        if (q == 0) {
            cn = (sp[r] + sp[NN+r]) + (sp[2*NN+r] + sp[3*NN+r]);
            sc[r] = cn;
        }
        __syncthreads();
    }
    if (q == 0) g_h[(b*NG + g)*NN + r] = cn;
}

// ============================================================
// Kernel 4: boundary prefix, 512 threads, 4-way split-K.
// C_{g+1} = Ad^S * C_g + h_g.  One block per batch.
// ============================================================
__global__ __launch_bounds__(NT) void k_phaseB() {
    extern __shared__ float sm[];
    float* sA = sm;             // NN*129
    float* sc = sA + NN*129;    // NN
    float* sp = sc + NN;        // NT
    int tid = threadIdx.x;
    int r = tid & (NN-1), q = tid >> 7;
    int b = blockIdx.x;
    const float* AdS = g_pow[1];   // Ad^32 after 5 squarings
    for (int idx = tid; idx < NN*NN; idx += NT) {
        int i = idx >> 7, j = idx & (NN-1);
        sA[i*129 + j] = AdS[idx];
    }
    if (tid < NN) sc[tid] = 0.0f;
    __syncthreads();
    float a[32];
    #pragma unroll
    for (int u = 0; u < 32; u++) a[u] = sA[r*129 + 32*q + u];

    float cn = 0.0f;
    for (int g = 0; g < NG; g++) {
        if (q == 0) g_bound[(b*NG + g)*NN + r] = cn;
        float acc0 = (q == 0) ? __ldg(g_h + (b*NG + g)*NN + r) : 0.f;
        float acc1 = 0.f, acc2 = 0.f, acc3 = 0.f;
        const float4* sc4 = (const float4*)sc;
        #pragma unroll
        for (int u4 = 0; u4 < 8; u4++) {
            float4 v = sc4[8*q + u4];
            acc0 = fmaf(a[4*u4+0], v.x, acc0);
            acc1 = fmaf(a[4*u4+1], v.y, acc1);
            acc2 = fmaf(a[4*u4+2], v.z, acc2);
            acc3 = fmaf(a[4*u4+3], v.w, acc3);
        }
        sp[q*NN + r] = (acc0 + acc1) + (acc2 + acc3);
        __syncthreads();
        if (q == 0) {
            cn = (sp[r] + sp[NN+r]) + (sp[2*NN+r] + sp[3*NN+r]);
            sc[r] = cn;
        }
        __syncthreads();
    }
}

// ============================================================
// Kernel 5: FUSED phase C + expand, 512 threads.
// Split-K matvec + all 512 threads stream the 64KB output tile.
// ============================================================
__global__ __launch_bounds__(NT) void k_fusedC(const float* __restrict__ f,
                                               const float* __restrict__ Cv,
                                               const float* __restrict__ Dv,
                                               float* __restrict__ ys,
                                               float* __restrict__ cfin) {
    extern __shared__ float sm[];
    float* sAd = sm;               // NN*129
    float* sc  = sAd + NN*129;     // NN
    float* sf  = sc + NN;          // CH
    float* sC  = sf + CH;          // NN
    float* sp  = sC + NN;          // NT
    int tid = threadIdx.x;
    int r = tid & (NN-1), q = tid >> 7;
    int g = blockIdx.x, b = blockIdx.y;

    for (int idx = tid; idx < NN*NN; idx += NT) {
        int i = idx >> 7, j = idx & (NN-1);
        sAd[i*129 + j] = g_Ad[idx];
    }
    if (tid < CH) sf[tid] = f[b*LL + g*CH + tid];
    if (tid < NN) {
        sC[tid] = Cv[tid];
        sc[tid] = g_bound[(b*NG + g)*NN + tid];
    }
    __syncthreads();

    float a[32];
    #pragma unroll
    for (int u = 0; u < 32; u++) a[u] = sAd[r*129 + 32*q + u];
    float bd  = (q == 0) ? g_Bd[r] : 0.0f;
    float dv0 = Dv[0];
    float4* outbase = (float4*)(ys + (size_t)(b*LL + g*CH) * NN * NN);

    for (int t = 0; t < CH; t++) {
        float ft = sf[t];
        float acc0 = (q == 0) ? bd * ft : 0.f;
        float acc1 = 0.f, acc2 = 0.f, acc3 = 0.f;
        const float4* sc4 = (const float4*)sc;
        #pragma unroll
        for (int u4 = 0; u4 < 8; u4++) {
            float4 v = sc4[8*q + u4];
            acc0 = fmaf(a[4*u4+0], v.x, acc0);
            acc1 = fmaf(a[4*u4+1], v.y, acc1);
            acc2 = fmaf(a[4*u4+2], v.z, acc2);
            acc3 = fmaf(a[4*u4+3], v.w, acc3);
        }
        sp[q*NN + r] = (acc0 + acc1) + (acc2 + acc3);
        __syncthreads();
        if (q == 0)
            sc[r] = (sp[r] + sp[NN+r]) + (sp[2*NN+r] + sp[3*NN+r]);
        __syncthreads();
        // stream the 64KB output tile for time t (coalesced STG.128)
        float df = dv0 * ft;
        float4* out = outbase + (size_t)t * (NN*NN/4);
        const float4* scv = (const float4*)sc;
        #pragma unroll
        for (int it = 0; it < 8; it++) {
            int idx = tid + NT*it;           // 0..4095 float4s
            float4 cv = scv[idx & 31];
            float  c_ = sC[idx >> 5];
            float4 v;
            v.x = fmaf(c_, cv.x, df);
            v.y = fmaf(c_, cv.y, df);
            v.z = fmaf(c_, cv.z, df);
            v.w = fmaf(c_, cv.w, df);
            out[idx] = v;
        }
    }
    if (cfin != nullptr && g == NG-1 && tid < NN)
        cfin[b*NN + tid] = sc[tid];
}

// ============================================================
extern "C" void kernel_launch(void* const* d_in, const int* in_sizes, int n_in,
                              void* d_out, int out_size) {
    const float* f = (const float*)d_in[0];
    const float* A = (const float*)d_in[1];
    const float* B = (const float*)d_in[2];
    const float* C = (const float*)d_in[3];
    const float* D = (const float*)d_in[4];
    float* out = (float*)d_out;

    const long long ysz = (long long)BATCH * LL * NN * NN;   // 67108864
    const int cf = BATCH * NN;                               // 256
    float* cfin = nullptr;
    float* ys   = out;
    if ((long long)out_size == ysz + cf) { cfin = out; ys = out + cf; }

    const int smem_disc = 2*NN*NN*4;                      // 131072
    const int smem_pA   = (NN*129 + NN + CH + NT)*4;      // ~68.7KB
    const int smem_pB   = (NN*129 + NN + NT)*4;           // ~68.6KB
    const int smem_fC   = (NN*129 + NN + CH + NN + NT)*4; // ~69.2KB
    cudaFuncSetAttribute(k_disc,   cudaFuncAttributeMaxDynamicSharedMemorySize, smem_disc);
    cudaFuncSetAttribute(k_phaseA, cudaFuncAttributeMaxDynamicSharedMemorySize, smem_pA);
    cudaFuncSetAttribute(k_phaseB, cudaFuncAttributeMaxDynamicSharedMemorySize, smem_pB);
    cudaFuncSetAttribute(k_fusedC, cudaFuncAttributeMaxDynamicSharedMemorySize, smem_fC);

    // 1) discretize
    k_disc<<<1, 1024, smem_disc>>>(A, B);
    // 2) phase A — local chunk contributions
    dim3 gA(NG, BATCH);
    k_phaseA<<<gA, NT, smem_pA>>>(f);
    // 3) Ad^32 via 5 squarings: pow0 -> pow1 -> pow0 -> pow1 -> pow0 -> pow1
    k_sq<<<NN, NN>>>(0, 1);
    k_sq<<<NN, NN>>>(1, 0);
    k_sq<<<NN, NN>>>(0, 1);
    k_sq<<<NN, NN>>>(1, 0);
    k_sq<<<NN, NN>>>(0, 1);
    // 4) boundary prefix (sequential over 64 chunks, per-batch block)
    k_phaseB<<<BATCH, NT, smem_pB>>>();
    // 5) fused phase C + expand: recompute states, stream 268MB of ys
    k_fusedC<<<gA, NT, smem_fC>>>(f, C, D, ys, cfin);
}

// round 7
// speedup vs baseline: 1.7234x; 1.4733x over previous
#include <cuda_runtime.h>

#define NN    128
#define BATCH 2
#define LL    2048
#define CH    32          // chunk length S
#define NG    (LL/CH)     // 64 chunks per batch
#define NT    512         // threads for split-K kernels
#define PIT   129         // smem pitch (conflict-free columns: 129 % 32 == 1)

// ---- device scratch (no allocation allowed) ----
__device__ float g_Ad[NN*NN];
__device__ float g_Bd[NN];
__device__ float g_pow[2][NN*NN];      // for Ad^S via squaring
__device__ float g_h[BATCH*NG*NN];     // local chunk contributions
__device__ float g_bound[BATCH*NG*NN]; // state entering each chunk

// ============================================================
// Kernel 1: discretize via divide-and-conquer triangular inverse.
// P1 = I - 0.5A is LOWER TRIANGULAR.
//   base: invert 16 8x8 diagonal blocks (parallel, 1 barrier)
//   4 combine levels s=8,16,32,64:  Minv21 = -Minv22*L21*Minv11
// Ad = 2*Minv - I, Bd = Minv*B.   9 barriers total (vs 127).
// ============================================================
__global__ __launch_bounds__(1024, 1) void k_disc(const float* __restrict__ A,
                                                  const float* __restrict__ B) {
    extern __shared__ float sm[];
    float* sP = sm;                 // NN*PIT  original P1
    float* sM = sm + NN*PIT;        // NN*PIT  Minv (lower), upper zeroed
    float* sT = sm + 2*NN*PIT;      // 4096 temp
    int tid = threadIdx.x;

    for (int idx = tid; idx < NN*NN; idx += 1024) {
        int i = idx >> 7, j = idx & (NN-1);
        float iv = (i == j) ? 1.0f : 0.0f;
        sP[i*PIT + j] = iv - 0.5f * A[idx];
        sM[i*PIT + j] = 0.0f;
    }
    __syncthreads();

    // base: 16 blocks of 8x8; thread = (blk, col) forward substitution
    if (tid < 128) {
        int blk = tid >> 3, col = tid & 7;
        int b0 = blk * 8;
        float x[8];
        #pragma unroll
        for (int i = 0; i < 8; i++) x[i] = 0.0f;
        for (int i = col; i < 8; i++) {
            float v = (i == col) ? 1.0f : 0.0f;
            for (int k = col; k < i; k++)
                v -= sP[(b0+i)*PIT + b0 + k] * x[k];
            x[i] = v / sP[(b0+i)*PIT + b0 + i];
        }
        #pragma unroll
        for (int i = 0; i < 8; i++)
            sM[(b0+i)*PIT + b0 + col] = x[i];
    }
    __syncthreads();

    // combine levels
    for (int s = 8; s <= 64; s <<= 1) {
        int npairs = NN / (2*s);
        int total  = npairs * s * s;          // <= 4096
        // T = Minv22 * L21
        for (int idx = tid; idx < total; idx += 1024) {
            int p = idx / (s*s);
            int rem = idx - p*s*s;
            int i = rem / s, j = rem - i*s;
            int r0 = 2*p*s;
            float acc = 0.0f;
            for (int k = 0; k < s; k++)
                acc = fmaf(sM[(r0+s+i)*PIT + r0+s+k],
                           sP[(r0+s+k)*PIT + r0+j], acc);
            sT[idx] = acc;
        }
        __syncthreads();
        // Minv21 = -T * Minv11
        for (int idx = tid; idx < total; idx += 1024) {
            int p = idx / (s*s);
            int rem = idx - p*s*s;
            int i = rem / s, j = rem - i*s;
            int r0 = 2*p*s;
            float acc = 0.0f;
            const float* tp = sT + p*s*s + i*s;
            for (int k = 0; k < s; k++)
                acc = fmaf(tp[k], sM[(r0+k)*PIT + r0+j], acc);
            sM[(r0+s+i)*PIT + r0+j] = -acc;
        }
        __syncthreads();
    }

    // outputs
    for (int idx = tid; idx < NN*NN; idx += 1024) {
        int i = idx >> 7, j = idx & (NN-1);
        float m = sM[i*PIT + j];
        float ad = 2.0f * m - ((i == j) ? 1.0f : 0.0f);
        g_Ad[idx] = ad;
        g_pow[0][idx] = ad;
    }
    if (tid < NN) {
        float acc = 0.0f;
        for (int j = 0; j <= tid; j++)            // Minv lower-triangular
            acc = fmaf(sM[tid*PIT + j], B[j], acc);
        g_Bd[tid] = acc;
    }
}

// ============================================================
// Kernel 2: matrix squaring. 16 blocks x 256 threads; block = 8 rows.
// launch_bounds(256,1) -> no reg cap -> unroll-8 float4 loads (MLP 8).
// ============================================================
__global__ __launch_bounds__(256, 1) void k_sq(int srcSel, int dstSel) {
    __shared__ float sa[8][NN];
    const float* __restrict__ src = g_pow[srcSel];
    float*       __restrict__ dst = g_pow[dstSel];
    int tid = threadIdx.x;
    int i0  = blockIdx.x * 8;
    for (int idx = tid; idx < 8*NN; idx += 256)
        sa[idx >> 7][idx & (NN-1)] = src[(i0 + (idx >> 7))*NN + (idx & (NN-1))];
    __syncthreads();
    int ri = tid >> 5;          // 0..7 row
    int jc = tid & 31;          // float4 column
    const float4* s4 = (const float4*)src;
    float4 acc = make_float4(0.f, 0.f, 0.f, 0.f);
    #pragma unroll
    for (int kk = 0; kk < NN; kk += 8) {
        float4 bv[8];
        #pragma unroll
        for (int u = 0; u < 8; u++)
            bv[u] = __ldg(s4 + (kk+u)*(NN/4) + jc);   // 8 x LDG.128 in flight
        #pragma unroll
        for (int u = 0; u < 8; u++) {
            float a = sa[ri][kk+u];
            acc.x = fmaf(a, bv[u].x, acc.x);
            acc.y = fmaf(a, bv[u].y, acc.y);
            acc.z = fmaf(a, bv[u].z, acc.z);
            acc.w = fmaf(a, bv[u].w, acc.w);
        }
    }
    ((float4*)dst)[(i0 + ri)*(NN/4) + jc] = acc;
}

// ============================================================
// Kernel 3: phase A, 512 threads, 4-way split-K.
// Thread (r = tid&127, q = tid>>7) owns Ad[r, 32q:32q+32] in regs.
// ============================================================
__global__ __launch_bounds__(NT, 1) void k_phaseA(const float* __restrict__ f) {
    extern __shared__ float sm[];
    float* sAd = sm;               // NN*PIT
    float* sc  = sAd + NN*PIT;     // NN
    float* sf  = sc + NN;          // CH
    float* sp  = sf + CH;          // NT partials
    int tid = threadIdx.x;
    int r = tid & (NN-1), q = tid >> 7;
    int g = blockIdx.x, b = blockIdx.y;

    for (int idx = tid; idx < NN*NN; idx += NT) {
        int i = idx >> 7, j = idx & (NN-1);
        sAd[i*PIT + j] = g_Ad[idx];
    }
    if (tid < CH) sf[tid] = f[b*LL + g*CH + tid];
    if (tid < NN) sc[tid] = 0.0f;
    __syncthreads();

    float a[32];
    #pragma unroll
    for (int u = 0; u < 32; u++) a[u] = sAd[r*PIT + 32*q + u];
    float bd = (q == 0) ? g_Bd[r] : 0.0f;

    float cn = 0.0f;
    for (int t = 0; t < CH; t++) {
        float acc0 = (q == 0) ? bd * sf[t] : 0.f;
        float acc1 = 0.f, acc2 = 0.f, acc3 = 0.f;
        const float4* sc4 = (const float4*)sc;
        #pragma unroll
        for (int u4 = 0; u4 < 8; u4++) {
            float4 v = sc4[8*q + u4];              // warp-broadcast
            acc0 = fmaf(a[4*u4+0], v.x, acc0);
            acc1 = fmaf(a[4*u4+1], v.y, acc1);
            acc2 = fmaf(a[4*u4+2], v.z, acc2);
            acc3 = fmaf(a[4*u4+3], v.w, acc3);
        }
        sp[q*NN + r] = (acc0 + acc1) + (acc2 + acc3);
        __syncthreads();
        if (q == 0) {
            cn = (sp[r] + sp[NN+r]) + (sp[2*NN+r] + sp[3*NN+r]);
            sc[r] = cn;
        }
        __syncthreads();
    }
    if (q == 0) g_h[(b*NG + g)*NN + r] = cn;
}

// ============================================================
// Kernel 4: boundary prefix, 512 threads, 4-way split-K.
// C_{g+1} = Ad^S * C_g + h_g.  One block per batch.
// ============================================================
__global__ __launch_bounds__(NT, 1) void k_phaseB() {
    extern __shared__ float sm[];
    float* sA = sm;             // NN*PIT
    float* sc = sA + NN*PIT;    // NN
    float* sp = sc + NN;        // NT
    int tid = threadIdx.x;
    int r = tid & (NN-1), q = tid >> 7;
    int b = blockIdx.x;
    const float* AdS = g_pow[1];   // Ad^32 after 5 squarings
    for (int idx = tid; idx < NN*NN; idx += NT) {
        int i = idx >> 7, j = idx & (NN-1);
        sA[i*PIT + j] = AdS[idx];
    }
    if (tid < NN) sc[tid] = 0.0f;
    __syncthreads();
    float a[32];
    #pragma unroll
    for (int u = 0; u < 32; u++) a[u] = sA[r*PIT + 32*q + u];

    float cn = 0.0f;
    for (int g = 0; g < NG; g++) {
        if (q == 0) g_bound[(b*NG + g)*NN + r] = cn;
        float acc0 = (q == 0) ? __ldg(g_h + (b*NG + g)*NN + r) : 0.f;
        float acc1 = 0.f, acc2 = 0.f, acc3 = 0.f;
        const float4* sc4 = (const float4*)sc;
        #pragma unroll
        for (int u4 = 0; u4 < 8; u4++) {
            float4 v = sc4[8*q + u4];
            acc0 = fmaf(a[4*u4+0], v.x, acc0);
            acc1 = fmaf(a[4*u4+1], v.y, acc1);
            acc2 = fmaf(a[4*u4+2], v.z, acc2);
            acc3 = fmaf(a[4*u4+3], v.w, acc3);
        }
        sp[q*NN + r] = (acc0 + acc1) + (acc2 + acc3);
        __syncthreads();
        if (q == 0) {
            cn = (sp[r] + sp[NN+r]) + (sp[2*NN+r] + sp[3*NN+r]);
            sc[r] = cn;
        }
        __syncthreads();
    }
}

// ============================================================
// Kernel 5: FUSED phase C + expand, TWO-PASS.
// Pass 1: 32-step recurrence into smem state buffer (barriers here).
// Pass 2: barrier-free store stream: per (thread,t): 1 LDS.128 + 8 STG.128.
// ============================================================
__global__ __launch_bounds__(NT, 1) void k_fusedC(const float* __restrict__ f,
                                                  const float* __restrict__ Cv,
                                                  const float* __restrict__ Dv,
                                                  float* __restrict__ ys,
                                                  float* __restrict__ cfin) {
    extern __shared__ float sm[];
    float* sAd = sm;               // NN*PIT
    float* sSt = sAd + NN*PIT;     // CH*NN states
    float* sc  = sSt + CH*NN;      // NN current state
    float* sf  = sc + NN;          // CH
    float* sC  = sf + CH;          // NN
    float* sp  = sC + NN;          // NT
    int tid = threadIdx.x;
    int r = tid & (NN-1), q = tid >> 7;
    int g = blockIdx.x, b = blockIdx.y;

    for (int idx = tid; idx < NN*NN; idx += NT) {
        int i = idx >> 7, j = idx & (NN-1);
        sAd[i*PIT + j] = g_Ad[idx];
    }
    if (tid < CH) sf[tid] = f[b*LL + g*CH + tid];
    if (tid < NN) {
        sC[tid] = Cv[tid];
        sc[tid] = g_bound[(b*NG + g)*NN + tid];
    }
    __syncthreads();

    float a[32];
    #pragma unroll
    for (int u = 0; u < 32; u++) a[u] = sAd[r*PIT + 32*q + u];
    float bd  = (q == 0) ? g_Bd[r] : 0.0f;
    float dv0 = Dv[0];

    // ---- pass 1: recurrence into sSt ----
    for (int t = 0; t < CH; t++) {
        float acc0 = (q == 0) ? bd * sf[t] : 0.f;
        float acc1 = 0.f, acc2 = 0.f, acc3 = 0.f;
        const float4* sc4 = (const float4*)sc;
        #pragma unroll
        for (int u4 = 0; u4 < 8; u4++) {
            float4 v = sc4[8*q + u4];
            acc0 = fmaf(a[4*u4+0], v.x, acc0);
            acc1 = fmaf(a[4*u4+1], v.y, acc1);
            acc2 = fmaf(a[4*u4+2], v.z, acc2);
            acc3 = fmaf(a[4*u4+3], v.w, acc3);
        }
        sp[q*NN + r] = (acc0 + acc1) + (acc2 + acc3);
        __syncthreads();
        if (q == 0) {
            float cn = (sp[r] + sp[NN+r]) + (sp[2*NN+r] + sp[3*NN+r]);
            sc[r] = cn;
            sSt[t*NN + r] = cn;
        }
        __syncthreads();
    }

    // ---- pass 2: barrier-free store stream ----
    float cn_[8];
    int nb = tid >> 5;
    #pragma unroll
    for (int it = 0; it < 8; it++) cn_[it] = sC[nb + 16*it];
    int lane = tid & 31;
    float4* outbase = (float4*)(ys + (size_t)(b*LL + g*CH) * NN * NN);
    const float4* st4 = (const float4*)sSt;

    for (int t = 0; t < CH; t++) {
        float4 cv = st4[t*(NN/4) + lane];
        float  df = dv0 * sf[t];
        float4* out = outbase + (size_t)t * (NN*NN/4);
        #pragma unroll
        for (int it = 0; it < 8; it++) {
            int idx = tid + NT*it;
            float4 v;
            v.x = fmaf(cn_[it], cv.x, df);
            v.y = fmaf(cn_[it], cv.y, df);
            v.z = fmaf(cn_[it], cv.z, df);
            v.w = fmaf(cn_[it], cv.w, df);
            out[idx] = v;
        }
    }
    if (cfin != nullptr && g == NG-1 && tid < NN)
        cfin[b*NN + tid] = sSt[(CH-1)*NN + tid];
}

// ============================================================
extern "C" void kernel_launch(void* const* d_in, const int* in_sizes, int n_in,
                              void* d_out, int out_size) {
    const float* f = (const float*)d_in[0];
    const float* A = (const float*)d_in[1];
    const float* B = (const float*)d_in[2];
    const float* C = (const float*)d_in[3];
    const float* D = (const float*)d_in[4];
    float* out = (float*)d_out;

    const long long ysz = (long long)BATCH * LL * NN * NN;   // 67108864
    const int cf = BATCH * NN;                               // 256
    float* cfin = nullptr;
    float* ys   = out;
    if ((long long)out_size == ysz + cf) { cfin = out; ys = out + cf; }

    const int smem_disc = (2*NN*PIT + 4096)*4;              // ~148.5KB
    const int smem_pA   = (NN*PIT + NN + CH + NT)*4;        // ~68.7KB
    const int smem_pB   = (NN*PIT + NN + NT)*4;             // ~68.6KB
    const int smem_fC   = (NN*PIT + CH*NN + NN + CH + NN + NT)*4; // ~85.5KB
    cudaFuncSetAttribute(k_disc,   cudaFuncAttributeMaxDynamicSharedMemorySize, smem_disc);
    cudaFuncSetAttribute(k_phaseA, cudaFuncAttributeMaxDynamicSharedMemorySize, smem_pA);
    cudaFuncSetAttribute(k_phaseB, cudaFuncAttributeMaxDynamicSharedMemorySize, smem_pB);
    cudaFuncSetAttribute(k_fusedC, cudaFuncAttributeMaxDynamicSharedMemorySize, smem_fC);

    // 1) discretize (D&C triangular inverse)
    k_disc<<<1, 1024, smem_disc>>>(A, B);
    // 2) phase A — local chunk contributions
    dim3 gA(NG, BATCH);
    k_phaseA<<<gA, NT, smem_pA>>>(f);
    // 3) Ad^32 via 5 squarings: pow0 -> pow1 -> pow0 -> pow1 -> pow0 -> pow1
    k_sq<<<16, 256>>>(0, 1);
    k_sq<<<16, 256>>>(1, 0);
    k_sq<<<16, 256>>>(0, 1);
    k_sq<<<16, 256>>>(1, 0);
    k_sq<<<16, 256>>>(0, 1);
    // 4) boundary prefix (sequential over 64 chunks, per-batch block)
    k_phaseB<<<BATCH, NT, smem_pB>>>();
    // 5) fused phase C + expand: recompute states, stream 268MB of ys
    k_fusedC<<<gA, NT, smem_fC>>>(f, C, D, ys, cfin);
}

// round 8
// speedup vs baseline: 1.9238x; 1.1163x over previous
#include <cuda_runtime.h>

#define NN    128
#define BATCH 2
#define LL    2048
#define CH    32          // chunk length S
#define NG    (LL/CH)     // 64 chunks per batch
#define NT    512         // threads for split-K kernels
#define PIT   129         // smem pitch (conflict-free columns)

// ---- device scratch (no allocation allowed) ----
__device__ float g_Ad[NN*NN];
__device__ float g_Bd[NN];
__device__ float g_pow[2][NN*NN];      // for Ad^S via squaring
__device__ float g_h[BATCH*NG*NN];     // local chunk contributions
__device__ float g_bound[BATCH*NG*NN]; // state entering each chunk

// ============================================================
// Kernel 1: discretize via divide-and-conquer triangular inverse.
// P1 = I - 0.5A is LOWER TRIANGULAR.
//   base: invert 16 8x8 diagonal blocks (parallel, 1 barrier)
//   4 combine levels s=8,16,32,64:  Minv21 = -Minv22*L21*Minv11
// Ad = 2*Minv - I, Bd = Minv*B.   9 barriers total.
// ============================================================
__global__ __launch_bounds__(1024, 1) void k_disc(const float* __restrict__ A,
                                                  const float* __restrict__ B) {
    extern __shared__ float sm[];
    float* sP = sm;                 // NN*PIT  original P1
    float* sM = sm + NN*PIT;        // NN*PIT  Minv (lower), upper zeroed
    float* sT = sm + 2*NN*PIT;      // 4096 temp
    int tid = threadIdx.x;

    for (int idx = tid; idx < NN*NN; idx += 1024) {
        int i = idx >> 7, j = idx & (NN-1);
        float iv = (i == j) ? 1.0f : 0.0f;
        sP[i*PIT + j] = iv - 0.5f * A[idx];
        sM[i*PIT + j] = 0.0f;
    }
    __syncthreads();

    // base: 16 blocks of 8x8; thread = (blk, col) forward substitution
    if (tid < 128) {
        int blk = tid >> 3, col = tid & 7;
        int b0 = blk * 8;
        float x[8];
        #pragma unroll
        for (int i = 0; i < 8; i++) x[i] = 0.0f;
        for (int i = col; i < 8; i++) {
            float v = (i == col) ? 1.0f : 0.0f;
            for (int k = col; k < i; k++)
                v -= sP[(b0+i)*PIT + b0 + k] * x[k];
            x[i] = v / sP[(b0+i)*PIT + b0 + i];
        }
        #pragma unroll
        for (int i = 0; i < 8; i++)
            sM[(b0+i)*PIT + b0 + col] = x[i];
    }
    __syncthreads();

    // combine levels
    for (int s = 8; s <= 64; s <<= 1) {
        int npairs = NN / (2*s);
        int total  = npairs * s * s;          // <= 4096
        // T = Minv22 * L21
        for (int idx = tid; idx < total; idx += 1024) {
            int p = idx / (s*s);
            int rem = idx - p*s*s;
            int i = rem / s, j = rem - i*s;
            int r0 = 2*p*s;
            float acc = 0.0f;
            for (int k = 0; k < s; k++)
                acc = fmaf(sM[(r0+s+i)*PIT + r0+s+k],
                           sP[(r0+s+k)*PIT + r0+j], acc);
            sT[idx] = acc;
        }
        __syncthreads();
        // Minv21 = -T * Minv11
        for (int idx = tid; idx < total; idx += 1024) {
            int p = idx / (s*s);
            int rem = idx - p*s*s;
            int i = rem / s, j = rem - i*s;
            int r0 = 2*p*s;
            float acc = 0.0f;
            const float* tp = sT + p*s*s + i*s;
            for (int k = 0; k < s; k++)
                acc = fmaf(tp[k], sM[(r0+k)*PIT + r0+j], acc);
            sM[(r0+s+i)*PIT + r0+j] = -acc;
        }
        __syncthreads();
    }

    // outputs
    for (int idx = tid; idx < NN*NN; idx += 1024) {
        int i = idx >> 7, j = idx & (NN-1);
        float m = sM[i*PIT + j];
        float ad = 2.0f * m - ((i == j) ? 1.0f : 0.0f);
        g_Ad[idx] = ad;
        g_pow[0][idx] = ad;
    }
    if (tid < NN) {
        float acc = 0.0f;
        for (int j = 0; j <= tid; j++)            // Minv lower-triangular
            acc = fmaf(sM[tid*PIT + j], B[j], acc);
        g_Bd[tid] = acc;
    }
}

// ============================================================
// Kernel 2: matrix squaring, SMEM-staged.
// 128 blocks x 128 threads. Block stages all of src (64KB) in smem
// with one wave of 32 independent LDG.128/thread, then computes one
// row purely from smem (broadcast a, conflict-free column reads).
// ============================================================
__global__ __launch_bounds__(NN, 1) void k_sq(int srcSel, int dstSel) {
    extern __shared__ float smq[];    // NN*NN
    float* sB = smq;
    const float4* s4 = (const float4*)g_pow[srcSel];
    float* __restrict__ dst = g_pow[dstSel];
    int i = blockIdx.x, tid = threadIdx.x;
    float4* sB4 = (float4*)sB;
    #pragma unroll
    for (int u = 0; u < 32; u++)
        sB4[tid + NN*u] = __ldg(s4 + tid + NN*u);   // 32 LDG.128 in flight
    __syncthreads();
    const float* arow = sB + i*NN;
    float acc0 = 0.f, acc1 = 0.f, acc2 = 0.f, acc3 = 0.f;
    #pragma unroll 16
    for (int k = 0; k < NN; k += 4) {
        acc0 = fmaf(arow[k+0], sB[(k+0)*NN + tid], acc0);
        acc1 = fmaf(arow[k+1], sB[(k+1)*NN + tid], acc1);
        acc2 = fmaf(arow[k+2], sB[(k+2)*NN + tid], acc2);
        acc3 = fmaf(arow[k+3], sB[(k+3)*NN + tid], acc3);
    }
    dst[i*NN + tid] = (acc0 + acc1) + (acc2 + acc3);
}

// ============================================================
// Kernel 3: phase A, 512 threads, 4-way split-K.
// Thread (r = tid&127, q = tid>>7) owns Ad[r, 32q:32q+32] in regs.
// ============================================================
__global__ __launch_bounds__(NT, 1) void k_phaseA(const float* __restrict__ f) {
    extern __shared__ float sm[];
    float* sAd = sm;               // NN*PIT
    float* sc  = sAd + NN*PIT;     // NN
    float* sf  = sc + NN;          // CH
    float* sp  = sf + CH;          // NT partials
    int tid = threadIdx.x;
    int r = tid & (NN-1), q = tid >> 7;
    int g = blockIdx.x, b = blockIdx.y;

    for (int idx = tid; idx < NN*NN; idx += NT) {
        int i = idx >> 7, j = idx & (NN-1);
        sAd[i*PIT + j] = g_Ad[idx];
    }
    if (tid < CH) sf[tid] = f[b*LL + g*CH + tid];
    if (tid < NN) sc[tid] = 0.0f;
    __syncthreads();

    float a[32];
    #pragma unroll
    for (int u = 0; u < 32; u++) a[u] = sAd[r*PIT + 32*q + u];
    float bd = (q == 0) ? g_Bd[r] : 0.0f;

    float cn = 0.0f;
    for (int t = 0; t < CH; t++) {
        float acc0 = (q == 0) ? bd * sf[t] : 0.f;
        float acc1 = 0.f, acc2 = 0.f, acc3 = 0.f;
        const float4* sc4 = (const float4*)sc;
        #pragma unroll
        for (int u4 = 0; u4 < 8; u4++) {
            float4 v = sc4[8*q + u4];              // warp-broadcast
            acc0 = fmaf(a[4*u4+0], v.x, acc0);
            acc1 = fmaf(a[4*u4+1], v.y, acc1);
            acc2 = fmaf(a[4*u4+2], v.z, acc2);
            acc3 = fmaf(a[4*u4+3], v.w, acc3);
        }
        sp[q*NN + r] = (acc0 + acc1) + (acc2 + acc3);
        __syncthreads();
        if (q == 0) {
            cn = (sp[r] + sp[NN+r]) + (sp[2*NN+r] + sp[3*NN+r]);
            sc[r] = cn;
        }
        __syncthreads();
    }
    if (q == 0) g_h[(b*NG + g)*NN + r] = cn;
}

// ============================================================
// Kernel 4: boundary prefix, 512 threads, 4-way split-K.
// C_{g+1} = Ad^S * C_g + h_g.  One block per batch.
// ============================================================
__global__ __launch_bounds__(NT, 1) void k_phaseB() {
    extern __shared__ float sm[];
    float* sA = sm;             // NN*PIT
    float* sc = sA + NN*PIT;    // NN
    float* sp = sc + NN;        // NT
    int tid = threadIdx.x;
    int r = tid & (NN-1), q = tid >> 7;
    int b = blockIdx.x;
    const float* AdS = g_pow[1];   // Ad^32 after 5 squarings
    for (int idx = tid; idx < NN*NN; idx += NT) {
        int i = idx >> 7, j = idx & (NN-1);
        sA[i*PIT + j] = AdS[idx];
    }
    if (tid < NN) sc[tid] = 0.0f;
    __syncthreads();
    float a[32];
    #pragma unroll
    for (int u = 0; u < 32; u++) a[u] = sA[r*PIT + 32*q + u];

    float cn = 0.0f;
    for (int g = 0; g < NG; g++) {
        if (q == 0) g_bound[(b*NG + g)*NN + r] = cn;
        float acc0 = (q == 0) ? __ldg(g_h + (b*NG + g)*NN + r) : 0.f;
        float acc1 = 0.f, acc2 = 0.f, acc3 = 0.f;
        const float4* sc4 = (const float4*)sc;
        #pragma unroll
        for (int u4 = 0; u4 < 8; u4++) {
            float4 v = sc4[8*q + u4];
            acc0 = fmaf(a[4*u4+0], v.x, acc0);
            acc1 = fmaf(a[4*u4+1], v.y, acc1);
            acc2 = fmaf(a[4*u4+2], v.z, acc2);
            acc3 = fmaf(a[4*u4+3], v.w, acc3);
        }
        sp[q*NN + r] = (acc0 + acc1) + (acc2 + acc3);
        __syncthreads();
        if (q == 0) {
            cn = (sp[r] + sp[NN+r]) + (sp[2*NN+r] + sp[3*NN+r]);
            sc[r] = cn;
        }
        __syncthreads();
    }
}

// ============================================================
// Kernel 5: FUSED phase C + expand, TWO-PASS.
// Pass 1: 32-step recurrence into smem state buffer (barriers here).
// Pass 2: barrier-free streaming store: per (thread,t): 1 LDS.128 + 8 STG.128.
// ============================================================
__global__ __launch_bounds__(NT, 1) void k_fusedC(const float* __restrict__ f,
                                                  const float* __restrict__ Cv,
                                                  const float* __restrict__ Dv,
                                                  float* __restrict__ ys,
                                                  float* __restrict__ cfin) {
    extern __shared__ float sm[];
    float* sAd = sm;               // NN*PIT
    float* sSt = sAd + NN*PIT;     // CH*NN states
    float* sc  = sSt + CH*NN;      // NN current state
    float* sf  = sc + NN;          // CH
    float* sC  = sf + CH;          // NN
    float* sp  = sC + NN;          // NT
    int tid = threadIdx.x;
    int r = tid & (NN-1), q = tid >> 7;
    int g = blockIdx.x, b = blockIdx.y;

    for (int idx = tid; idx < NN*NN; idx += NT) {
        int i = idx >> 7, j = idx & (NN-1);
        sAd[i*PIT + j] = g_Ad[idx];
    }
    if (tid < CH) sf[tid] = f[b*LL + g*CH + tid];
    if (tid < NN) {
        sC[tid] = Cv[tid];
        sc[tid] = g_bound[(b*NG + g)*NN + tid];
    }
    __syncthreads();

    float a[32];
    #pragma unroll
    for (int u = 0; u < 32; u++) a[u] = sAd[r*PIT + 32*q + u];
    float bd  = (q == 0) ? g_Bd[r] : 0.0f;
    float dv0 = Dv[0];

    // ---- pass 1: recurrence into sSt ----
    for (int t = 0; t < CH; t++) {
        float acc0 = (q == 0) ? bd * sf[t] : 0.f;
        float acc1 = 0.f, acc2 = 0.f, acc3 = 0.f;
        const float4* sc4 = (const float4*)sc;
        #pragma unroll
        for (int u4 = 0; u4 < 8; u4++) {
            float4 v = sc4[8*q + u4];
            acc0 = fmaf(a[4*u4+0], v.x, acc0);
            acc1 = fmaf(a[4*u4+1], v.y, acc1);
            acc2 = fmaf(a[4*u4+2], v.z, acc2);
            acc3 = fmaf(a[4*u4+3], v.w, acc3);
        }
        sp[q*NN + r] = (acc0 + acc1) + (acc2 + acc3);
        __syncthreads();
        if (q == 0) {
            float cn = (sp[r] + sp[NN+r]) + (sp[2*NN+r] + sp[3*NN+r]);
            sc[r] = cn;
            sSt[t*NN + r] = cn;
        }
        __syncthreads();
    }

    // ---- pass 2: barrier-free streaming store ----
    float cn_[8];
    int nb = tid >> 5;
    #pragma unroll
    for (int it = 0; it < 8; it++) cn_[it] = sC[nb + 16*it];
    int lane = tid & 31;
    float4* outbase = (float4*)(ys + (size_t)(b*LL + g*CH) * NN * NN);
    const float4* st4 = (const float4*)sSt;

    for (int t = 0; t < CH; t++) {
        float4 cv = st4[t*(NN/4) + lane];
        float  df = dv0 * sf[t];
        float4* out = outbase + (size_t)t * (NN*NN/4);
        #pragma unroll
        for (int it = 0; it < 8; it++) {
            int idx = tid + NT*it;
            float4 v;
            v.x = fmaf(cn_[it], cv.x, df);
            v.y = fmaf(cn_[it], cv.y, df);
            v.z = fmaf(cn_[it], cv.z, df);
            v.w = fmaf(cn_[it], cv.w, df);
            __stcs(&out[idx], v);               // streaming (evict-first) store
        }
    }
    if (cfin != nullptr && g == NG-1 && tid < NN)
        cfin[b*NN + tid] = sSt[(CH-1)*NN + tid];
}

// ============================================================
extern "C" void kernel_launch(void* const* d_in, const int* in_sizes, int n_in,
                              void* d_out, int out_size) {
    const float* f = (const float*)d_in[0];
    const float* A = (const float*)d_in[1];
    const float* B = (const float*)d_in[2];
    const float* C = (const float*)d_in[3];
    const float* D = (const float*)d_in[4];
    float* out = (float*)d_out;

    const long long ysz = (long long)BATCH * LL * NN * NN;   // 67108864
    const int cf = BATCH * NN;                               // 256
    float* cfin = nullptr;
    float* ys   = out;
    if ((long long)out_size == ysz + cf) { cfin = out; ys = out + cf; }

    const int smem_disc = (2*NN*PIT + 4096)*4;              // ~148.5KB
    const int smem_sq   = NN*NN*4;                          // 65536
    const int smem_pA   = (NN*PIT + NN + CH + NT)*4;        // ~68.7KB
    const int smem_pB   = (NN*PIT + NN + NT)*4;             // ~68.6KB
    const int smem_fC   = (NN*PIT + CH*NN + NN + CH + NN + NT)*4; // ~85.5KB
    cudaFuncSetAttribute(k_disc,   cudaFuncAttributeMaxDynamicSharedMemorySize, smem_disc);
    cudaFuncSetAttribute(k_sq,     cudaFuncAttributeMaxDynamicSharedMemorySize, smem_sq);
    cudaFuncSetAttribute(k_phaseA, cudaFuncAttributeMaxDynamicSharedMemorySize, smem_pA);
    cudaFuncSetAttribute(k_phaseB, cudaFuncAttributeMaxDynamicSharedMemorySize, smem_pB);
    cudaFuncSetAttribute(k_fusedC, cudaFuncAttributeMaxDynamicSharedMemorySize, smem_fC);

    // 1) discretize (D&C triangular inverse)
    k_disc<<<1, 1024, smem_disc>>>(A, B);
    // 2) phase A — local chunk contributions
    dim3 gA(NG, BATCH);
    k_phaseA<<<gA, NT, smem_pA>>>(f);
    // 3) Ad^32 via 5 squarings: pow0 -> pow1 -> pow0 -> pow1 -> pow0 -> pow1
    k_sq<<<NN, NN, smem_sq>>>(0, 1);
    k_sq<<<NN, NN, smem_sq>>>(1, 0);
    k_sq<<<NN, NN, smem_sq>>>(0, 1);
    k_sq<<<NN, NN, smem_sq>>>(1, 0);
    k_sq<<<NN, NN, smem_sq>>>(0, 1);
    // 4) boundary prefix (sequential over 64 chunks, per-batch block)
    k_phaseB<<<BATCH, NT, smem_pB>>>();
    // 5) fused phase C + expand: recompute states, stream 268MB of ys
    k_fusedC<<<gA, NT, smem_fC>>>(f, C, D, ys, cfin);
}